// round 11
// baseline (speedup 1.0000x reference)
#include <cuda_runtime.h>
#include <cstdint>

// Skinny GEMM via mma.sync tf32, high-occupancy direct-LDG mainloop.
// C[65536,40] = embs[65536,1024] @ Wall^T, Wall = packed [W_status; W_flight; 0]
// R11: mt=1 (16 tokens/warp) cuts acc regs 40->20 so the kernel fits ~68 regs
// -> launch_bounds(128,7) -> 28 warps/SM (vs 16 before, which capped every
// previous variant). Grid 1024 CTAs = one perfectly balanced wave (7/SM).
// W packed into one __device__ array: single base pointer + immediate offsets,
// pad rows truly zero. No smem in mainloop -> L1D ~161KB -> Wall L1-resident.
// Raw fp32 bits as tf32 (RZ truncate), bias cancelled by corr in epilogue.

#define EMB    1024
#define NS     5
#define NF     30
#define NL     35
#define NROWS  40
#define OUTC   63
#define BM     64      // tokens per CTA (4 warps x 16)
#define LSTR   37      // odd stride -> conflict-free epilogue
#define NTH    128
#define NKB    (EMB / 16)    // 64 k16 blocks

__device__ float Wall[NROWS * EMB];   // 160KB packed weights (+zero pad rows)

__global__ void pack_w_kernel(const float* __restrict__ Ws,
                              const float* __restrict__ Wf) {
    int i = blockIdx.x * blockDim.x + threadIdx.x;
    if (i < NROWS * EMB) {
        int row = i >> 10, col = i & (EMB - 1);
        float v = 0.0f;
        if (row < NS)      v = Ws[row * EMB + col];
        else if (row < NL) v = Wf[(row - NS) * EMB + col];
        Wall[i] = v;
    }
}

__device__ __forceinline__ void mma8(float* c, const uint32_t* a, const uint32_t* b) {
    asm volatile(
        "mma.sync.aligned.m16n8k8.row.col.f32.tf32.tf32.f32 "
        "{%0,%1,%2,%3}, {%4,%5,%6,%7}, {%8,%9}, {%0,%1,%2,%3};"
        : "+f"(c[0]), "+f"(c[1]), "+f"(c[2]), "+f"(c[3])
        : "r"(a[0]), "r"(a[1]), "r"(a[2]), "r"(a[3]), "r"(b[0]), "r"(b[1]));
}

__global__ __launch_bounds__(NTH, 7) void aux2_hiocc_kernel(
    const float* __restrict__ embs,
    const float* __restrict__ b_status,
    const float* __restrict__ b_flight,
    float* __restrict__ out,
    int ntok)
{
    __shared__ float Ls[BM * LSTR];   // 9.5KB, epilogue only

    const int tid  = threadIdx.x;
    const int wid  = tid >> 5;
    const int lane = tid & 31;
    const int g    = lane >> 2;     // 0..7
    const int t    = lane & 3;      // 0..3
    const long tokw = (long)blockIdx.x * BM + wid * 16;  // warp's 16 tokens

    // single base pointers; all row/kb displacement via immediate offsets
    const float* Abase = embs + (tokw + g) * EMB + 4 * t;     // rows g, g+8
    const float* Bbase = Wall + g * EMB + 4 * t;              // rows nt*8+g

    float acc[5][4];
#pragma unroll
    for (int nt = 0; nt < 5; ++nt)
#pragma unroll
        for (int i = 0; i < 4; ++i) acc[nt][i] = 0.0f;

    // prime the 1-deep A register pipeline
    uint4 a0n = *(const uint4*)(Abase);
    uint4 a1n = *(const uint4*)(Abase + 8 * EMB);

#pragma unroll 4
    for (int kb = 0; kb < NKB; ++kb) {
        uint4 a0 = a0n, a1 = a1n;
        if (kb + 1 < NKB) {
            a0n = *(const uint4*)(Abase + (kb + 1) * 16);
            a1n = *(const uint4*)(Abase + 8 * EMB + (kb + 1) * 16);
        }

        // B: 5 LDG.128, L1-resident (Wall fits L1D since smem is tiny)
        uint4 b[5];
#pragma unroll
        for (int nt = 0; nt < 5; ++nt)
            b[nt] = *(const uint4*)(Bbase + nt * 8 * EMB + kb * 16);

        // K-permutation: slots {t,t+4} = cols {4t,4t+1}; {4t+2,4t+3} next
        uint32_t af0[4] = { a0.x, a1.x, a0.y, a1.y };
        uint32_t af1[4] = { a0.z, a1.z, a0.w, a1.w };

#pragma unroll
        for (int nt = 0; nt < 5; ++nt) {
            uint32_t bf0[2] = { b[nt].x, b[nt].y };
            uint32_t bf1[2] = { b[nt].z, b[nt].w };
            mma8(acc[nt], af0, bf0);
            mma8(acc[nt], af1, bf1);
        }
    }

    // ---- epilogue: fragments -> logits smem ----
    {
        int r0 = wid * 16 + g;
#pragma unroll
        for (int nt = 0; nt < 5; ++nt) {
            int cc = nt * 8 + t * 2;
            if (cc < NL) {
                Ls[r0 * LSTR + cc]       = acc[nt][0];
                Ls[(r0 + 8) * LSTR + cc] = acc[nt][2];
            }
            if (cc + 1 < NL) {
                Ls[r0 * LSTR + cc + 1]       = acc[nt][1];
                Ls[(r0 + 8) * LSTR + cc + 1] = acc[nt][3];
            }
        }
    }
    __syncthreads();

    // ---- dual softmax + store: threads 0..63 own one token each ----
    if (tid < BM) {
        const float corr = 1.000677f;   // tf32 RZ truncation bias compensation
        float sl[NS], fl[NF];
#pragma unroll
        for (int n = 0; n < NS; ++n) sl[n] = Ls[tid * LSTR + n] * corr + b_status[n];
#pragma unroll
        for (int n = 0; n < NF; ++n) fl[n] = Ls[tid * LSTR + NS + n] * corr + b_flight[n];

        float smax = sl[0];
#pragma unroll
        for (int n = 1; n < NS; ++n) smax = fmaxf(smax, sl[n]);
        float ssum = 0.f;
#pragma unroll
        for (int n = 0; n < NS; ++n) { sl[n] = __expf(sl[n] - smax); ssum += sl[n]; }
        float sinv = 1.f / ssum;
#pragma unroll
        for (int n = 0; n < NS; ++n) sl[n] *= sinv;

        float fm = fl[0];
#pragma unroll
        for (int n = 1; n < NF; ++n) fm = fmaxf(fm, fl[n]);
        float fsum = 0.f;
#pragma unroll
        for (int n = 0; n < NF; ++n) { fl[n] = __expf(fl[n] - fm); fsum += fl[n]; }
        float finv = 1.f / fsum;
#pragma unroll
        for (int n = 0; n < NF; ++n) fl[n] *= finv;

        const float book = sl[4], change = sl[3];
        long token = (long)blockIdx.x * BM + tid;
        if (token < ntok) {
            float* op = out + token * (long)OUTC;
            op[0] = sl[0];
            op[1] = sl[2];
            op[2] = sl[1];
#pragma unroll
            for (int j = 0; j < NF; ++j) {
                op[3 + j]  = book   * fl[j];
                op[33 + j] = change * fl[j];
            }
        }
    }
}

extern "C" void kernel_launch(void* const* d_in, const int* in_sizes, int n_in,
                              void* d_out, int out_size) {
    const float* embs     = (const float*)d_in[0];
    const float* W_status = (const float*)d_in[1];
    const float* b_status = (const float*)d_in[2];
    const float* W_flight = (const float*)d_in[3];
    const float* b_flight = (const float*)d_in[4];
    float* out = (float*)d_out;

    // pack weights into padded __device__ array (deterministic, capturable)
    pack_w_kernel<<<(NROWS * EMB + 255) / 256, 256>>>(W_status, W_flight);

    int ntok = in_sizes[0] / EMB;   // 65536
    int blocks = ntok / BM;         // 1024
    aux2_hiocc_kernel<<<blocks, NTH>>>(embs, b_status, b_flight, out, ntok);
}